// round 3
// baseline (speedup 1.0000x reference)
#include <cuda_runtime.h>
#include <math.h>
#include <stdint.h>

// ---------------- problem constants ----------------
#define BATCH 4
#define SEQ   2048
#define HID   2048
#define NEXP  32
#define INTER 2048
#define TOPK  4
#define NTOK  (BATCH*SEQ)          // 8192
#define NPAIR (NTOK*TOPK)          // 32768
#define MAXTILES (NPAIR/128 + NEXP) // 288

// ---------------- GEMM tiling ----------------
#define BM 128
#define BN 256
#define BK 16
#define PADK 20   // row stride (floats): 80B; (r*20+q)%32 covers all banks conflict-free

// dynamic smem layout (floats)
#define A_STG (BM*PADK)            // 2560
#define B_STG (BN*PADK)            // 5120
#define OFF_B (2*A_STG)            // A[0],A[1],B[0],B[1],arow
#define OFF_AROW (2*A_STG + 2*B_STG)
#define SMEM_FLOATS (OFF_AROW + BM)
#define SMEM_BYTES (SMEM_FLOATS*4)

// ---------------- device scratch (static: no allocation allowed) ----------------
__device__ int   g_counts[NEXP];
__device__ int   g_fill[NEXP];
__device__ int   g_offsets[NEXP+1];
__device__ int   g_topk_ids[NPAIR];
__device__ float g_topk_w[NPAIR];
__device__ int   g_perm_token[NPAIR];
__device__ float g_pair_w[NPAIR];
__device__ int   g_pair_pos[NPAIR];
__device__ int   g_tile_expert[MAXTILES];
__device__ int   g_tile_row0[MAXTILES];
__device__ int   g_num_tiles;

__device__ float g_inter[(size_t)NPAIR*INTER];     // silu(g)*u   (256 MB)
__device__ float g_pair_out[(size_t)NPAIR*HID];    // per-pair out (256 MB)

// ---------------- helpers ----------------
__device__ __forceinline__ uint32_t f2tf32(float x) {
    uint32_t r;
    asm("cvt.rna.tf32.f32 %0, %1;" : "=r"(r) : "f"(x));
    return r;
}

__device__ __forceinline__ void mma_tf32(float* c, const uint32_t* a, const uint32_t* b) {
    asm volatile(
        "mma.sync.aligned.m16n8k8.row.col.f32.tf32.tf32.f32 "
        "{%0,%1,%2,%3}, {%4,%5,%6,%7}, {%8,%9}, {%0,%1,%2,%3};\n"
        : "+f"(c[0]), "+f"(c[1]), "+f"(c[2]), "+f"(c[3])
        : "r"(a[0]), "r"(a[1]), "r"(a[2]), "r"(a[3]),
          "r"(b[0]), "r"(b[1]));
}

__device__ __forceinline__ void cp16(float* dst_smem, const float* src_gmem, bool pred) {
    uint32_t s = (uint32_t)__cvta_generic_to_shared(dst_smem);
    int sz = pred ? 16 : 0;  // src_size=0 -> zero-fill 16B
    asm volatile("cp.async.cg.shared.global [%0], [%1], 16, %2;\n"
                 :: "r"(s), "l"(src_gmem), "r"(sz));
}

// ---------------- routing ----------------
__global__ void route_kernel(const float* __restrict__ logits) {
    int t = blockIdx.x * blockDim.x + threadIdx.x;
    if (t >= NTOK) return;
    const float* row = logits + (size_t)t * NEXP;

    float v[TOPK]; int id[TOPK];
    #pragma unroll
    for (int k = 0; k < TOPK; k++) { v[k] = -1e30f; id[k] = 0; }

    for (int e = 0; e < NEXP; e++) {
        float x = row[e];
        if (x > v[TOPK-1]) {
            int p = TOPK - 1;
            while (p > 0 && x > v[p-1]) { v[p] = v[p-1]; id[p] = id[p-1]; p--; }
            v[p] = x; id[p] = e;
        }
    }
    float w[TOPK]; float s = 0.f;
    #pragma unroll
    for (int k = 0; k < TOPK; k++) { w[k] = expf(v[k] - v[0]); s += w[k]; }
    float inv = 1.f / s;
    #pragma unroll
    for (int k = 0; k < TOPK; k++) {
        g_topk_ids[t*TOPK + k] = id[k];
        g_topk_w[t*TOPK + k]   = w[k] * inv;
        atomicAdd(&g_counts[id[k]], 1);
    }
}

__global__ void zero_kernel() {
    int i = threadIdx.x;
    if (i < NEXP) { g_counts[i] = 0; g_fill[i] = 0; }
}

__global__ void scan_tiles_kernel() {
    if (threadIdx.x != 0) return;
    int off = 0, nt = 0;
    for (int e = 0; e < NEXP; e++) {
        g_offsets[e] = off;
        int c = g_counts[e];
        for (int r = 0; r < c; r += BM) {
            g_tile_expert[nt] = e;
            g_tile_row0[nt]   = off + r;
            nt++;
        }
        off += c;
    }
    g_offsets[NEXP] = off;
    g_num_tiles = nt;
}

__global__ void scatter_kernel() {
    int i = blockIdx.x * blockDim.x + threadIdx.x;
    if (i >= NPAIR) return;
    int e = g_topk_ids[i];
    int pos = g_offsets[e] + atomicAdd(&g_fill[e], 1);
    g_perm_token[pos] = i >> 2;
    g_pair_w[pos]     = g_topk_w[i];
    g_pair_pos[i]     = pos;
}

// ---------------- grouped NT GEMM (tf32 mma.sync, 128x256 CTA tile) ----------------
// MODE 1: g_inter[pos, j] = silu(gate)*up,  gate/up from gather(x) @ w13[e]^T
//         (w13 rows gather-interleaved at load: tile row 2j = gate j, 2j+1 = up j)
// MODE 2: g_pair_out[pos, h] = pair_w[pos] * (g_inter[pos,:] @ w2[e]^T)
template<int MODE>
__global__ __launch_bounds__(256, 1)
void gemm_nt(const float* __restrict__ Ain, const float* __restrict__ Wall) {
    constexpr int KD = (MODE == 1) ? HID : INTER;   // 2048 both
    constexpr int KT = KD / BK;                     // 128

    int tile = blockIdx.y;
    if (tile >= g_num_tiles) return;
    int e    = g_tile_expert[tile];
    int row0 = g_tile_row0[tile];
    int m_valid = g_offsets[e+1] - row0;
    if (m_valid > BM) m_valid = BM;
    int n0 = blockIdx.x * BN;

    extern __shared__ float smem[];
    float* As[2] = { smem,            smem + A_STG };
    float* Bs[2] = { smem + OFF_B,    smem + OFF_B + B_STG };
    int*   s_arow = (int*)(smem + OFF_AROW);

    int tid = threadIdx.x;
    const float* A = (MODE == 1) ? Ain : g_inter;

    // A-row gather table
    for (int r = tid; r < BM; r += 256) {
        int gr = -1;
        if (r < m_valid) gr = (MODE == 1) ? g_perm_token[row0 + r] : (row0 + r);
        s_arow[r] = gr;
    }
    __syncthreads();

    // expert weight base; per-row source mapping handled in loader
    const float* We = Wall + (size_t)e * ((MODE == 1) ? (size_t)2*INTER*KD : (size_t)HID*KD);

    int wid = tid >> 5, lane = tid & 31;
    int warp_m = wid >> 2, warp_n = wid & 3;     // 2 x 4 warps -> 64x64 warp tiles
    int g = lane >> 2, q = lane & 3;

    float acc[4][8][4];
    #pragma unroll
    for (int a = 0; a < 4; a++)
        #pragma unroll
        for (int b = 0; b < 8; b++)
            #pragma unroll
            for (int c = 0; c < 4; c++) acc[a][b][c] = 0.f;

    // ---- stage loader: A 512 chunks (2/thr), B 1024 chunks (4/thr) ----
    auto load_stage = [&](int stage, int kt) {
        float* Ad = As[stage];
        float* Bd = Bs[stage];
        #pragma unroll
        for (int i = 0; i < 2; i++) {
            int idx = tid + i*256;
            int r = idx >> 2, c = idx & 3;
            int gr = s_arow[r];
            const float* src = A + (size_t)(gr < 0 ? 0 : gr) * KD + kt + c*4;
            cp16(Ad + r*PADK + c*4, src, gr >= 0);
        }
        #pragma unroll
        for (int i = 0; i < 4; i++) {
            int idx = tid + i*256;
            int r = idx >> 2, c = idx & 3;
            int br;
            if (MODE == 1) {
                int j = (n0 + r) >> 1;                 // n0 even
                br = (r & 1) ? (INTER + j) : j;        // interleave gate/up
            } else {
                br = n0 + r;
            }
            const float* src = We + (size_t)br * KD + kt + c*4;
            cp16(Bd + r*PADK + c*4, src, true);
        }
        asm volatile("cp.async.commit_group;\n");
    };

    load_stage(0, 0);

    for (int it = 0; it < KT; it++) {
        int cur = it & 1;
        if (it + 1 < KT) {
            load_stage(cur ^ 1, (it + 1) * BK);
            asm volatile("cp.async.wait_group 1;\n");
        } else {
            asm volatile("cp.async.wait_group 0;\n");
        }
        __syncthreads();

        const float* Ab = As[cur];
        const float* Bb = Bs[cur];
        #pragma unroll
        for (int ks = 0; ks < 2; ks++) {
            int k0 = ks * 8;
            uint32_t af[4][4], bf[8][2];
            #pragma unroll
            for (int mt = 0; mt < 4; mt++) {
                int r = warp_m*64 + mt*16 + g;
                af[mt][0] = f2tf32(Ab[(r    )*PADK + k0 + q    ]);
                af[mt][1] = f2tf32(Ab[(r + 8)*PADK + k0 + q    ]);
                af[mt][2] = f2tf32(Ab[(r    )*PADK + k0 + q + 4]);
                af[mt][3] = f2tf32(Ab[(r + 8)*PADK + k0 + q + 4]);
            }
            #pragma unroll
            for (int nt = 0; nt < 8; nt++) {
                int bn = warp_n*64 + nt*8 + g;
                bf[nt][0] = f2tf32(Bb[bn*PADK + k0 + q    ]);
                bf[nt][1] = f2tf32(Bb[bn*PADK + k0 + q + 4]);
            }
            #pragma unroll
            for (int mt = 0; mt < 4; mt++)
                #pragma unroll
                for (int nt = 0; nt < 8; nt++)
                    mma_tf32(acc[mt][nt], af[mt], bf[nt]);
        }
        __syncthreads();
    }

    // ---- epilogue ----
    #pragma unroll
    for (int mt = 0; mt < 4; mt++) {
        #pragma unroll
        for (int h = 0; h < 2; h++) {
            int lr = warp_m*64 + mt*16 + g + h*8;
            if (lr < m_valid) {
                int grow = row0 + lr;
                if (MODE == 1) {
                    // cols 2m, 2m+1 = (gate, up) pair -> inter col m
                    float* dst = g_inter + (size_t)grow * INTER + (n0 >> 1) + warp_n*32;
                    #pragma unroll
                    for (int nt = 0; nt < 8; nt++) {
                        float gv = acc[mt][nt][h*2 + 0];
                        float uv = acc[mt][nt][h*2 + 1];
                        dst[nt*4 + q] = gv / (1.f + expf(-gv)) * uv;
                    }
                } else {
                    float sc = g_pair_w[grow];
                    float* dst = g_pair_out + (size_t)grow * HID + n0 + warp_n*64;
                    #pragma unroll
                    for (int nt = 0; nt < 8; nt++) {
                        float2 v;
                        v.x = acc[mt][nt][h*2 + 0] * sc;
                        v.y = acc[mt][nt][h*2 + 1] * sc;
                        *(float2*)(dst + nt*8 + 2*q) = v;
                    }
                }
            }
        }
    }
}

// ---------------- deterministic combine ----------------
__global__ void combine_kernel(float* __restrict__ out) {
    int t = blockIdx.x;
    int p0 = g_pair_pos[t*4 + 0];
    int p1 = g_pair_pos[t*4 + 1];
    int p2 = g_pair_pos[t*4 + 2];
    int p3 = g_pair_pos[t*4 + 3];
    const float4* r0 = (const float4*)(g_pair_out + (size_t)p0 * HID);
    const float4* r1 = (const float4*)(g_pair_out + (size_t)p1 * HID);
    const float4* r2 = (const float4*)(g_pair_out + (size_t)p2 * HID);
    const float4* r3 = (const float4*)(g_pair_out + (size_t)p3 * HID);
    float4* o = (float4*)(out + (size_t)t * HID);
    for (int c = threadIdx.x; c < HID/4; c += blockDim.x) {
        float4 a = r0[c], b = r1[c], cc = r2[c], d = r3[c];
        float4 v;
        v.x = a.x + b.x + cc.x + d.x;
        v.y = a.y + b.y + cc.y + d.y;
        v.z = a.z + b.z + cc.z + d.z;
        v.w = a.w + b.w + cc.w + d.w;
        o[c] = v;
    }
}

// ---------------- launch ----------------
extern "C" void kernel_launch(void* const* d_in, const int* in_sizes, int n_in,
                              void* d_out, int out_size) {
    const float* x      = (const float*)d_in[0];
    const float* logits = (const float*)d_in[1];
    const float* w13    = (const float*)d_in[2];
    const float* w2     = (const float*)d_in[3];
    float* out = (float*)d_out;

    cudaFuncSetAttribute((const void*)gemm_nt<1>,
                         cudaFuncAttributeMaxDynamicSharedMemorySize, SMEM_BYTES);
    cudaFuncSetAttribute((const void*)gemm_nt<2>,
                         cudaFuncAttributeMaxDynamicSharedMemorySize, SMEM_BYTES);

    zero_kernel<<<1, 32>>>();
    route_kernel<<<(NTOK + 255)/256, 256>>>(logits);
    scan_tiles_kernel<<<1, 1>>>();
    scatter_kernel<<<(NPAIR + 255)/256, 256>>>();

    gemm_nt<1><<<dim3((2*INTER)/BN, MAXTILES), 256, SMEM_BYTES>>>(x, w13);
    gemm_nt<2><<<dim3(HID/BN, MAXTILES), 256, SMEM_BYTES>>>(nullptr, w2);

    combine_kernel<<<NTOK, 128>>>(out);
}

// round 4
// speedup vs baseline: 1.2119x; 1.2119x over previous
#include <cuda_runtime.h>
#include <math.h>
#include <stdint.h>

// ---------------- problem constants ----------------
#define BATCH 4
#define SEQ   2048
#define HID   2048
#define NEXP  32
#define INTER 2048
#define TOPK  4
#define NTOK  (BATCH*SEQ)          // 8192
#define NPAIR (NTOK*TOPK)          // 32768
#define MAXTILES (NPAIR/128 + NEXP) // 288

// ---------------- GEMM tiling (R1-proven shape) ----------------
#define BM 128
#define BN 128
#define BK 16
#define PADK 20   // row stride (floats): 80B, conflict-free fragment access

#define A_STG (BM*PADK)            // 2560 floats
#define B_STG (BN*PADK)            // 2560 floats
#define OFF_B (2*A_STG)
#define OFF_AROW (2*A_STG + 2*B_STG)
#define SMEM_FLOATS (OFF_AROW + BM)
#define SMEM_BYTES (SMEM_FLOATS*4)  // ~41.5 KB -> 2 CTAs/SM

// ---------------- device scratch (static: no allocation allowed) ----------------
__device__ int   g_counts[NEXP];
__device__ int   g_fill[NEXP];
__device__ int   g_offsets[NEXP+1];
__device__ int   g_topk_ids[NPAIR];
__device__ float g_topk_w[NPAIR];
__device__ int   g_perm_token[NPAIR];
__device__ float g_pair_w[NPAIR];
__device__ int   g_pair_pos[NPAIR];
__device__ int   g_tile_expert[MAXTILES];
__device__ int   g_tile_row0[MAXTILES];
__device__ int   g_num_tiles;

__device__ float g_xr[(size_t)NTOK*HID];            // rounded x        (64 MB)
__device__ float g_w13r[(size_t)NEXP*2*INTER*HID];  // rounded w13      (1 GB)
__device__ float g_w2r[(size_t)NEXP*HID*INTER];     // rounded w2       (512 MB)
__device__ float g_inter[(size_t)NPAIR*INTER];      // silu(g)*u rounded(256 MB)
__device__ float g_pair_out[(size_t)NPAIR*HID];     // per-pair out     (256 MB)

// ---------------- helpers ----------------
__device__ __forceinline__ uint32_t f2tf32(float x) {
    uint32_t r;
    asm("cvt.rna.tf32.f32 %0, %1;" : "=r"(r) : "f"(x));
    return r;
}

__device__ __forceinline__ void mma_tf32(float* c, const uint32_t* a, const uint32_t* b) {
    asm volatile(
        "mma.sync.aligned.m16n8k8.row.col.f32.tf32.tf32.f32 "
        "{%0,%1,%2,%3}, {%4,%5,%6,%7}, {%8,%9}, {%0,%1,%2,%3};\n"
        : "+f"(c[0]), "+f"(c[1]), "+f"(c[2]), "+f"(c[3])
        : "r"(a[0]), "r"(a[1]), "r"(a[2]), "r"(a[3]),
          "r"(b[0]), "r"(b[1]));
}

__device__ __forceinline__ void cp16(float* dst_smem, const float* src_gmem, bool pred) {
    uint32_t s = (uint32_t)__cvta_generic_to_shared(dst_smem);
    int sz = pred ? 16 : 0;  // src_size=0 -> zero-fill 16B
    asm volatile("cp.async.cg.shared.global [%0], [%1], 16, %2;\n"
                 :: "r"(s), "l"(src_gmem), "r"(sz));
}

// ---------------- routing ----------------
__global__ void route_kernel(const float* __restrict__ logits) {
    int t = blockIdx.x * blockDim.x + threadIdx.x;
    if (t >= NTOK) return;
    const float* row = logits + (size_t)t * NEXP;

    float v[TOPK]; int id[TOPK];
    #pragma unroll
    for (int k = 0; k < TOPK; k++) { v[k] = -1e30f; id[k] = 0; }

    for (int e = 0; e < NEXP; e++) {
        float x = row[e];
        if (x > v[TOPK-1]) {
            int p = TOPK - 1;
            while (p > 0 && x > v[p-1]) { v[p] = v[p-1]; id[p] = id[p-1]; p--; }
            v[p] = x; id[p] = e;
        }
    }
    float w[TOPK]; float s = 0.f;
    #pragma unroll
    for (int k = 0; k < TOPK; k++) { w[k] = expf(v[k] - v[0]); s += w[k]; }
    float inv = 1.f / s;
    #pragma unroll
    for (int k = 0; k < TOPK; k++) {
        g_topk_ids[t*TOPK + k] = id[k];
        g_topk_w[t*TOPK + k]   = w[k] * inv;
        atomicAdd(&g_counts[id[k]], 1);
    }
}

__global__ void zero_kernel() {
    int i = threadIdx.x;
    if (i < NEXP) { g_counts[i] = 0; g_fill[i] = 0; }
}

__global__ void scan_tiles_kernel() {
    if (threadIdx.x != 0) return;
    int off = 0, nt = 0;
    for (int e = 0; e < NEXP; e++) {
        g_offsets[e] = off;
        int c = g_counts[e];
        for (int r = 0; r < c; r += BM) {
            g_tile_expert[nt] = e;
            g_tile_row0[nt]   = off + r;
            nt++;
        }
        off += c;
    }
    g_offsets[NEXP] = off;
    g_num_tiles = nt;
}

__global__ void scatter_kernel() {
    int i = blockIdx.x * blockDim.x + threadIdx.x;
    if (i >= NPAIR) return;
    int e = g_topk_ids[i];
    int pos = g_offsets[e] + atomicAdd(&g_fill[e], 1);
    g_perm_token[pos] = i >> 2;
    g_pair_w[pos]     = g_topk_w[i];
    g_pair_pos[i]     = pos;
}

// ---------------- tf32 pre-rounding passes (elementwise, streaming) ----------------
__global__ void round_kernel(const float* __restrict__ src, float* __restrict__ dst) {
    size_t i = (size_t)blockIdx.x * blockDim.x + threadIdx.x;
    float4 v = ((const float4*)src)[i];
    float4 o;
    o.x = __uint_as_float(f2tf32(v.x));
    o.y = __uint_as_float(f2tf32(v.y));
    o.z = __uint_as_float(f2tf32(v.z));
    o.w = __uint_as_float(f2tf32(v.w));
    ((float4*)dst)[i] = o;
}

// ---------------- grouped NT GEMM (tf32 mma.sync, pre-rounded operands) ----------------
// MODE 1: g_inter[pos, j] = round_tf32(silu(gate)*up), gate/up = gather(g_xr) @ g_w13r[e]^T
//         (w13 rows interleaved at load: tile row 2j = gate j, 2j+1 = up j)
// MODE 2: g_pair_out[pos, h] = pair_w[pos] * (g_inter[pos,:] @ g_w2r[e]^T)
template<int MODE>
__global__ __launch_bounds__(256, 2)
void gemm_nt() {
    constexpr int KD = (MODE == 1) ? HID : INTER;   // 2048 both
    constexpr int KT = KD / BK;                     // 128

    int tile = blockIdx.y;
    if (tile >= g_num_tiles) return;
    int e    = g_tile_expert[tile];
    int row0 = g_tile_row0[tile];
    int m_valid = g_offsets[e+1] - row0;
    if (m_valid > BM) m_valid = BM;
    int n0 = blockIdx.x * BN;

    extern __shared__ float smem[];
    float* As[2] = { smem,         smem + A_STG };
    float* Bs[2] = { smem + OFF_B, smem + OFF_B + B_STG };
    int*   s_arow = (int*)(smem + OFF_AROW);

    int tid = threadIdx.x;
    const float* A = (MODE == 1) ? g_xr : g_inter;
    const float* We = ((MODE == 1) ? g_w13r : g_w2r)
                      + (size_t)e * ((MODE == 1) ? (size_t)2*INTER*KD : (size_t)HID*KD);

    for (int r = tid; r < BM; r += 256) {
        int gr = -1;
        if (r < m_valid) gr = (MODE == 1) ? g_perm_token[row0 + r] : (row0 + r);
        s_arow[r] = gr;
    }
    __syncthreads();

    int wid = tid >> 5, lane = tid & 31;
    int warp_m = wid >> 2, warp_n = wid & 3;       // 2 x 4 warps -> 64x32 warp tiles
    int g = lane >> 2, q = lane & 3;

    float acc[4][4][4];
    #pragma unroll
    for (int a = 0; a < 4; a++)
        #pragma unroll
        for (int b = 0; b < 4; b++)
            #pragma unroll
            for (int c = 0; c < 4; c++) acc[a][b][c] = 0.f;

    // ---- stage loader: A 512 chunks (2/thr), B 512 chunks (2/thr) ----
    auto load_stage = [&](int stage, int kt) {
        float* Ad = As[stage];
        float* Bd = Bs[stage];
        #pragma unroll
        for (int i = 0; i < 2; i++) {
            int idx = tid + i*256;
            int r = idx >> 2, c = idx & 3;
            int gr = s_arow[r];
            const float* src = A + (size_t)(gr < 0 ? 0 : gr) * KD + kt + c*4;
            cp16(Ad + r*PADK + c*4, src, gr >= 0);
        }
        #pragma unroll
        for (int i = 0; i < 2; i++) {
            int idx = tid + i*256;
            int r = idx >> 2, c = idx & 3;
            int br;
            if (MODE == 1) {
                int j = (n0 + r) >> 1;              // n0 even
                br = (r & 1) ? (INTER + j) : j;     // interleave gate/up rows
            } else {
                br = n0 + r;
            }
            const float* src = We + (size_t)br * KD + kt + c*4;
            cp16(Bd + r*PADK + c*4, src, true);
        }
        asm volatile("cp.async.commit_group;\n");
    };

    load_stage(0, 0);

    const uint32_t* dummy;
    for (int it = 0; it < KT; it++) {
        int cur = it & 1;
        if (it + 1 < KT) {
            load_stage(cur ^ 1, (it + 1) * BK);
            asm volatile("cp.async.wait_group 1;\n");
        } else {
            asm volatile("cp.async.wait_group 0;\n");
        }
        __syncthreads();

        const uint32_t* Ab = (const uint32_t*)As[cur];
        const uint32_t* Bb = (const uint32_t*)Bs[cur];
        #pragma unroll
        for (int ks = 0; ks < 2; ks++) {
            int k0 = ks * 8;
            uint32_t af[4][4], bf[4][2];
            #pragma unroll
            for (int mt = 0; mt < 4; mt++) {
                int r = warp_m*64 + mt*16 + g;
                af[mt][0] = Ab[(r    )*PADK + k0 + q    ];
                af[mt][1] = Ab[(r + 8)*PADK + k0 + q    ];
                af[mt][2] = Ab[(r    )*PADK + k0 + q + 4];
                af[mt][3] = Ab[(r + 8)*PADK + k0 + q + 4];
            }
            #pragma unroll
            for (int nt = 0; nt < 4; nt++) {
                int bn = warp_n*32 + nt*8 + g;
                bf[nt][0] = Bb[bn*PADK + k0 + q    ];
                bf[nt][1] = Bb[bn*PADK + k0 + q + 4];
            }
            #pragma unroll
            for (int mt = 0; mt < 4; mt++)
                #pragma unroll
                for (int nt = 0; nt < 4; nt++)
                    mma_tf32(acc[mt][nt], af[mt], bf[nt]);
        }
        __syncthreads();
    }

    // ---- epilogue ----
    #pragma unroll
    for (int mt = 0; mt < 4; mt++) {
        #pragma unroll
        for (int h = 0; h < 2; h++) {
            int lr = warp_m*64 + mt*16 + g + h*8;
            if (lr < m_valid) {
                int grow = row0 + lr;
                if (MODE == 1) {
                    // cols (2m, 2m+1) = (gate, up) -> inter col m; round for GEMM2
                    float* dst = g_inter + (size_t)grow * INTER + (n0 >> 1) + warp_n*16;
                    #pragma unroll
                    for (int nt = 0; nt < 4; nt++) {
                        float gv = acc[mt][nt][h*2 + 0];
                        float uv = acc[mt][nt][h*2 + 1];
                        float iv = gv / (1.f + expf(-gv)) * uv;
                        dst[nt*4 + q] = __uint_as_float(f2tf32(iv));
                    }
                } else {
                    float sc = g_pair_w[grow];
                    float* dst = g_pair_out + (size_t)grow * HID + n0 + warp_n*32;
                    #pragma unroll
                    for (int nt = 0; nt < 4; nt++) {
                        float2 v;
                        v.x = acc[mt][nt][h*2 + 0] * sc;
                        v.y = acc[mt][nt][h*2 + 1] * sc;
                        *(float2*)(dst + nt*8 + 2*q) = v;
                    }
                }
            }
        }
    }
}

// ---------------- deterministic combine ----------------
__global__ void combine_kernel(float* __restrict__ out) {
    int t = blockIdx.x;
    int p0 = g_pair_pos[t*4 + 0];
    int p1 = g_pair_pos[t*4 + 1];
    int p2 = g_pair_pos[t*4 + 2];
    int p3 = g_pair_pos[t*4 + 3];
    const float4* r0 = (const float4*)(g_pair_out + (size_t)p0 * HID);
    const float4* r1 = (const float4*)(g_pair_out + (size_t)p1 * HID);
    const float4* r2 = (const float4*)(g_pair_out + (size_t)p2 * HID);
    const float4* r3 = (const float4*)(g_pair_out + (size_t)p3 * HID);
    float4* o = (float4*)(out + (size_t)t * HID);
    for (int c = threadIdx.x; c < HID/4; c += blockDim.x) {
        float4 a = r0[c], b = r1[c], cc = r2[c], d = r3[c];
        float4 v;
        v.x = a.x + b.x + cc.x + d.x;
        v.y = a.y + b.y + cc.y + d.y;
        v.z = a.z + b.z + cc.z + d.z;
        v.w = a.w + b.w + cc.w + d.w;
        o[c] = v;
    }
}

// ---------------- launch ----------------
extern "C" void kernel_launch(void* const* d_in, const int* in_sizes, int n_in,
                              void* d_out, int out_size) {
    const float* x      = (const float*)d_in[0];
    const float* logits = (const float*)d_in[1];
    const float* w13    = (const float*)d_in[2];
    const float* w2     = (const float*)d_in[3];
    float* out = (float*)d_out;

    cudaFuncSetAttribute((const void*)gemm_nt<1>,
                         cudaFuncAttributeMaxDynamicSharedMemorySize, SMEM_BYTES);
    cudaFuncSetAttribute((const void*)gemm_nt<2>,
                         cudaFuncAttributeMaxDynamicSharedMemorySize, SMEM_BYTES);

    zero_kernel<<<1, 32>>>();
    route_kernel<<<(NTOK + 255)/256, 256>>>(logits);
    scan_tiles_kernel<<<1, 1>>>();
    scatter_kernel<<<(NPAIR + 255)/256, 256>>>();

    // pre-round operands to tf32 (streaming float4 passes)
    {
        size_t n_x   = (size_t)NTOK*HID/4;
        size_t n_w13 = (size_t)NEXP*2*INTER*HID/4;
        size_t n_w2  = (size_t)NEXP*HID*INTER/4;
        float* xr; float* w13r; float* w2r;
        cudaGetSymbolAddress((void**)&xr,   g_xr);
        cudaGetSymbolAddress((void**)&w13r, g_w13r);
        cudaGetSymbolAddress((void**)&w2r,  g_w2r);
        round_kernel<<<(int)(n_x/256),   256>>>(x,   xr);
        round_kernel<<<(int)(n_w13/256), 256>>>(w13, w13r);
        round_kernel<<<(int)(n_w2/256),  256>>>(w2,  w2r);
    }

    gemm_nt<1><<<dim3((2*INTER)/BN, MAXTILES), 256, SMEM_BYTES>>>();
    gemm_nt<2><<<dim3(HID/BN, MAXTILES), 256, SMEM_BYTES>>>();

    combine_kernel<<<NTOK, 128>>>(out);
}

// round 5
// speedup vs baseline: 2.2706x; 1.8736x over previous
#include <cuda_runtime.h>
#include <cuda_fp16.h>
#include <math.h>
#include <stdint.h>

// ---------------- problem constants ----------------
#define BATCH 4
#define SEQ   2048
#define HID   2048
#define NEXP  32
#define INTER 2048
#define TOPK  4
#define NTOK  (BATCH*SEQ)          // 8192
#define NPAIR (NTOK*TOPK)          // 32768
#define MAXTILES (NPAIR/128 + NEXP) // 288

// ---------------- GEMM tiling (fp16, m16n8k16) ----------------
#define BM 128
#define BN 128
#define BK 32                       // fp16: 32 halves = 16 u32 pairs per row
#define PADP 20                     // row stride in u32 pairs (80B) - conflict-free

#define A_STG (BM*PADP)             // 2560 u32
#define B_STG (BN*PADP)             // 2560 u32
#define OFF_B (2*A_STG)
#define OFF_AROW (2*A_STG + 2*B_STG)
#define SMEM_U32 (OFF_AROW + BM)
#define SMEM_BYTES (SMEM_U32*4)     // ~41.5 KB -> 2 CTAs/SM

// ---------------- device scratch (static: no allocation allowed) ----------------
__device__ int   g_counts[NEXP];
__device__ int   g_fill[NEXP];
__device__ int   g_offsets[NEXP+1];
__device__ int   g_topk_ids[NPAIR];
__device__ float g_topk_w[NPAIR];
__device__ int   g_perm_token[NPAIR];
__device__ float g_pair_w[NPAIR];
__device__ int   g_pair_pos[NPAIR];
__device__ int   g_tile_expert[MAXTILES];
__device__ int   g_tile_row0[MAXTILES];
__device__ int   g_num_tiles;

__device__ __half g_xh[(size_t)NTOK*HID];             // x as fp16         (32 MB)
__device__ __half g_w13h[(size_t)NEXP*2*INTER*HID];   // w13 fp16, rows interleaved (512 MB)
__device__ __half g_w2h[(size_t)NEXP*HID*INTER];      // w2 fp16           (256 MB)
__device__ __half g_ih[(size_t)NPAIR*INTER];          // silu(g)*u fp16    (128 MB)
__device__ float  g_pair_out[(size_t)NPAIR*HID];      // per-pair out f32  (256 MB)

// ---------------- helpers ----------------
__device__ __forceinline__ uint32_t pack2h(float a, float b) {
    __half2 h = __floats2half2_rn(a, b);
    return *(uint32_t*)&h;
}

__device__ __forceinline__ void mma_f16(float* c, const uint32_t* a, const uint32_t* b) {
    asm volatile(
        "mma.sync.aligned.m16n8k16.row.col.f32.f16.f16.f32 "
        "{%0,%1,%2,%3}, {%4,%5,%6,%7}, {%8,%9}, {%0,%1,%2,%3};\n"
        : "+f"(c[0]), "+f"(c[1]), "+f"(c[2]), "+f"(c[3])
        : "r"(a[0]), "r"(a[1]), "r"(a[2]), "r"(a[3]),
          "r"(b[0]), "r"(b[1]));
}

__device__ __forceinline__ void cp16(uint32_t* dst_smem, const void* src_gmem, bool pred) {
    uint32_t s = (uint32_t)__cvta_generic_to_shared(dst_smem);
    int sz = pred ? 16 : 0;  // src_size=0 -> zero-fill 16B
    asm volatile("cp.async.cg.shared.global [%0], [%1], 16, %2;\n"
                 :: "r"(s), "l"(src_gmem), "r"(sz));
}

// ---------------- routing ----------------
__global__ void route_kernel(const float* __restrict__ logits) {
    int t = blockIdx.x * blockDim.x + threadIdx.x;
    if (t >= NTOK) return;
    const float* row = logits + (size_t)t * NEXP;

    float v[TOPK]; int id[TOPK];
    #pragma unroll
    for (int k = 0; k < TOPK; k++) { v[k] = -1e30f; id[k] = 0; }

    for (int e = 0; e < NEXP; e++) {
        float x = row[e];
        if (x > v[TOPK-1]) {
            int p = TOPK - 1;
            while (p > 0 && x > v[p-1]) { v[p] = v[p-1]; id[p] = id[p-1]; p--; }
            v[p] = x; id[p] = e;
        }
    }
    float w[TOPK]; float s = 0.f;
    #pragma unroll
    for (int k = 0; k < TOPK; k++) { w[k] = expf(v[k] - v[0]); s += w[k]; }
    float inv = 1.f / s;
    #pragma unroll
    for (int k = 0; k < TOPK; k++) {
        g_topk_ids[t*TOPK + k] = id[k];
        g_topk_w[t*TOPK + k]   = w[k] * inv;
        atomicAdd(&g_counts[id[k]], 1);
    }
}

__global__ void zero_kernel() {
    int i = threadIdx.x;
    if (i < NEXP) { g_counts[i] = 0; g_fill[i] = 0; }
}

__global__ void scan_tiles_kernel() {
    if (threadIdx.x != 0) return;
    int off = 0, nt = 0;
    for (int e = 0; e < NEXP; e++) {
        g_offsets[e] = off;
        int c = g_counts[e];
        for (int r = 0; r < c; r += BM) {
            g_tile_expert[nt] = e;
            g_tile_row0[nt]   = off + r;
            nt++;
        }
        off += c;
    }
    g_offsets[NEXP] = off;
    g_num_tiles = nt;
}

__global__ void scatter_kernel() {
    int i = blockIdx.x * blockDim.x + threadIdx.x;
    if (i >= NPAIR) return;
    int e = g_topk_ids[i];
    int pos = g_offsets[e] + atomicAdd(&g_fill[e], 1);
    g_perm_token[pos] = i >> 2;
    g_pair_w[pos]     = g_topk_w[i];
    g_pair_pos[i]     = pos;
}

// ---------------- fp16 conversion passes (8 elems/thread) ----------------
__global__ void half_x_kernel(const float* __restrict__ src) {
    size_t i = (size_t)blockIdx.x * blockDim.x + threadIdx.x;
    float4 v0 = ((const float4*)src)[2*i];
    float4 v1 = ((const float4*)src)[2*i + 1];
    uint4 o;
    o.x = pack2h(v0.x, v0.y); o.y = pack2h(v0.z, v0.w);
    o.z = pack2h(v1.x, v1.y); o.w = pack2h(v1.z, v1.w);
    ((uint4*)g_xh)[i] = o;
}

// w13 [E, 2I, H] -> fp16 with rows interleaved: dst row 2j = gate j, 2j+1 = up j
__global__ void half_w13_kernel(const float* __restrict__ w13) {
    size_t i = (size_t)blockIdx.x * blockDim.x + threadIdx.x;   // 8-elem chunk idx
    const int ROWC = HID/8;                    // 256 chunks per row
    const size_t PERE = (size_t)(2*INTER) * ROWC;
    size_t e = i / PERE;
    size_t rem = i - e * PERE;
    int r = (int)(rem / ROWC);
    int c = (int)(rem % ROWC);
    int j = r >> 1;
    int srcrow = (r & 1) ? (INTER + j) : j;
    size_t sbase = (e * (size_t)(2*INTER) + srcrow) * ROWC + c;
    float4 v0 = ((const float4*)w13)[2*sbase];
    float4 v1 = ((const float4*)w13)[2*sbase + 1];
    uint4 o;
    o.x = pack2h(v0.x, v0.y); o.y = pack2h(v0.z, v0.w);
    o.z = pack2h(v1.x, v1.y); o.w = pack2h(v1.z, v1.w);
    ((uint4*)g_w13h)[i] = o;
}

__global__ void half_w2_kernel(const float* __restrict__ w2) {
    size_t i = (size_t)blockIdx.x * blockDim.x + threadIdx.x;
    float4 v0 = ((const float4*)w2)[2*i];
    float4 v1 = ((const float4*)w2)[2*i + 1];
    uint4 o;
    o.x = pack2h(v0.x, v0.y); o.y = pack2h(v0.z, v0.w);
    o.z = pack2h(v1.x, v1.y); o.w = pack2h(v1.z, v1.w);
    ((uint4*)g_w2h)[i] = o;
}

// ---------------- grouped NT GEMM (fp16 m16n8k16, fp32 accum) ----------------
// MODE 1: g_ih[pos, j] = fp16(silu(gate)*up), gate/up = gather(g_xh) @ g_w13h[e]^T
//         (w13 rows pre-interleaved: tile row 2j = gate j, 2j+1 = up j)
// MODE 2: g_pair_out[pos, h] = pair_w[pos] * (g_ih[pos,:] @ g_w2h[e]^T)
template<int MODE>
__global__ __launch_bounds__(256, 2)
void gemm_nt() {
    constexpr int KD = (MODE == 1) ? HID : INTER;   // 2048 both
    constexpr int KT = KD / BK;                     // 64

    int tile = blockIdx.x;
    if (tile >= g_num_tiles) return;
    int e    = g_tile_expert[tile];
    int row0 = g_tile_row0[tile];
    int m_valid = g_offsets[e+1] - row0;
    if (m_valid > BM) m_valid = BM;
    int n0 = blockIdx.y * BN;

    extern __shared__ uint32_t smem[];
    uint32_t* As[2] = { smem,         smem + A_STG };
    uint32_t* Bs[2] = { smem + OFF_B, smem + OFF_B + B_STG };
    int*      s_arow = (int*)(smem + OFF_AROW);

    int tid = threadIdx.x;
    const __half* Ah = (MODE == 1) ? g_xh : g_ih;
    const __half* We = ((MODE == 1) ? g_w13h : g_w2h)
                       + (size_t)e * ((MODE == 1) ? (size_t)2*INTER*KD : (size_t)HID*KD);

    for (int r = tid; r < BM; r += 256) {
        int gr = -1;
        if (r < m_valid) gr = (MODE == 1) ? g_perm_token[row0 + r] : (row0 + r);
        s_arow[r] = gr;
    }
    __syncthreads();

    int wid = tid >> 5, lane = tid & 31;
    int warp_m = wid >> 2, warp_n = wid & 3;       // 2 x 4 warps -> 64x32 warp tiles
    int g = lane >> 2, q = lane & 3;

    float acc[4][4][4];
    #pragma unroll
    for (int a = 0; a < 4; a++)
        #pragma unroll
        for (int b = 0; b < 4; b++)
            #pragma unroll
            for (int c = 0; c < 4; c++) acc[a][b][c] = 0.f;

    // ---- stage loader: A 512 16B-chunks (2/thr), B 512 (2/thr) ----
    auto load_stage = [&](int stage, int kt /*halves*/) {
        uint32_t* Ad = As[stage];
        uint32_t* Bd = Bs[stage];
        #pragma unroll
        for (int i = 0; i < 2; i++) {
            int idx = tid + i*256;
            int r = idx >> 2, c = idx & 3;
            int gr = s_arow[r];
            const __half* src = Ah + (size_t)(gr < 0 ? 0 : gr) * KD + kt + c*8;
            cp16(Ad + r*PADP + c*4, src, gr >= 0);
        }
        #pragma unroll
        for (int i = 0; i < 2; i++) {
            int idx = tid + i*256;
            int r = idx >> 2, c = idx & 3;
            const __half* src = We + (size_t)(n0 + r) * KD + kt + c*8;
            cp16(Bd + r*PADP + c*4, src, true);
        }
        asm volatile("cp.async.commit_group;\n");
    };

    load_stage(0, 0);

    for (int it = 0; it < KT; it++) {
        int cur = it & 1;
        if (it + 1 < KT) {
            load_stage(cur ^ 1, (it + 1) * BK);
            asm volatile("cp.async.wait_group 1;\n");
        } else {
            asm volatile("cp.async.wait_group 0;\n");
        }
        __syncthreads();

        const uint32_t* Ab = As[cur];
        const uint32_t* Bb = Bs[cur];
        #pragma unroll
        for (int kk = 0; kk < 2; kk++) {           // two k16 halves
            int kp = kk * 8;                       // pair offset
            uint32_t af[4][4], bf[4][2];
            #pragma unroll
            for (int mt = 0; mt < 4; mt++) {
                int r = warp_m*64 + mt*16 + g;
                af[mt][0] = Ab[(r    )*PADP + kp + q    ];
                af[mt][1] = Ab[(r + 8)*PADP + kp + q    ];
                af[mt][2] = Ab[(r    )*PADP + kp + q + 4];
                af[mt][3] = Ab[(r + 8)*PADP + kp + q + 4];
            }
            #pragma unroll
            for (int nt = 0; nt < 4; nt++) {
                int bn = warp_n*32 + nt*8 + g;
                bf[nt][0] = Bb[bn*PADP + kp + q    ];
                bf[nt][1] = Bb[bn*PADP + kp + q + 4];
            }
            #pragma unroll
            for (int mt = 0; mt < 4; mt++)
                #pragma unroll
                for (int nt = 0; nt < 4; nt++)
                    mma_f16(acc[mt][nt], af[mt], bf[nt]);
        }
        __syncthreads();
    }

    // ---- epilogue ----
    #pragma unroll
    for (int mt = 0; mt < 4; mt++) {
        #pragma unroll
        for (int h = 0; h < 2; h++) {
            int lr = warp_m*64 + mt*16 + g + h*8;
            if (lr < m_valid) {
                int grow = row0 + lr;
                if (MODE == 1) {
                    // cols (2m,2m+1) = (gate,up) -> inter col m (fp16)
                    __half* dst = g_ih + (size_t)grow * INTER + (n0 >> 1) + warp_n*16;
                    #pragma unroll
                    for (int nt = 0; nt < 4; nt++) {
                        float gv = acc[mt][nt][h*2 + 0];
                        float uv = acc[mt][nt][h*2 + 1];
                        float iv = gv / (1.f + expf(-gv)) * uv;
                        dst[nt*4 + q] = __float2half_rn(iv);
                    }
                } else {
                    float sc = g_pair_w[grow];
                    float* dst = g_pair_out + (size_t)grow * HID + n0 + warp_n*32;
                    #pragma unroll
                    for (int nt = 0; nt < 4; nt++) {
                        float2 v;
                        v.x = acc[mt][nt][h*2 + 0] * sc;
                        v.y = acc[mt][nt][h*2 + 1] * sc;
                        *(float2*)(dst + nt*8 + 2*q) = v;
                    }
                }
            }
        }
    }
}

// ---------------- deterministic combine ----------------
__global__ void combine_kernel(float* __restrict__ out) {
    int t = blockIdx.x;
    int p0 = g_pair_pos[t*4 + 0];
    int p1 = g_pair_pos[t*4 + 1];
    int p2 = g_pair_pos[t*4 + 2];
    int p3 = g_pair_pos[t*4 + 3];
    const float4* r0 = (const float4*)(g_pair_out + (size_t)p0 * HID);
    const float4* r1 = (const float4*)(g_pair_out + (size_t)p1 * HID);
    const float4* r2 = (const float4*)(g_pair_out + (size_t)p2 * HID);
    const float4* r3 = (const float4*)(g_pair_out + (size_t)p3 * HID);
    float4* o = (float4*)(out + (size_t)t * HID);
    for (int c = threadIdx.x; c < HID/4; c += blockDim.x) {
        float4 a = r0[c], b = r1[c], cc = r2[c], d = r3[c];
        float4 v;
        v.x = a.x + b.x + cc.x + d.x;
        v.y = a.y + b.y + cc.y + d.y;
        v.z = a.z + b.z + cc.z + d.z;
        v.w = a.w + b.w + cc.w + d.w;
        o[c] = v;
    }
}

// ---------------- launch ----------------
extern "C" void kernel_launch(void* const* d_in, const int* in_sizes, int n_in,
                              void* d_out, int out_size) {
    const float* x      = (const float*)d_in[0];
    const float* logits = (const float*)d_in[1];
    const float* w13    = (const float*)d_in[2];
    const float* w2     = (const float*)d_in[3];
    float* out = (float*)d_out;

    cudaFuncSetAttribute((const void*)gemm_nt<1>,
                         cudaFuncAttributeMaxDynamicSharedMemorySize, SMEM_BYTES);
    cudaFuncSetAttribute((const void*)gemm_nt<2>,
                         cudaFuncAttributeMaxDynamicSharedMemorySize, SMEM_BYTES);

    zero_kernel<<<1, 32>>>();
    route_kernel<<<(NTOK + 255)/256, 256>>>(logits);
    scan_tiles_kernel<<<1, 1>>>();
    scatter_kernel<<<(NPAIR + 255)/256, 256>>>();

    // fp16 conversion passes (8 elems per thread)
    half_x_kernel  <<<(int)(((size_t)NTOK*HID/8)       /256), 256>>>(x);
    half_w13_kernel<<<(int)(((size_t)NEXP*2*INTER*HID/8)/256), 256>>>(w13);
    half_w2_kernel <<<(int)(((size_t)NEXP*HID*INTER/8) /256), 256>>>(w2);

    gemm_nt<1><<<dim3(MAXTILES, (2*INTER)/BN), 256, SMEM_BYTES>>>();
    gemm_nt<2><<<dim3(MAXTILES, HID/BN), 256, SMEM_BYTES>>>();

    combine_kernel<<<NTOK, 128>>>(out);
}